// round 9
// baseline (speedup 1.0000x reference)
#include <cuda_runtime.h>
#include <cstdint>
#include <cstddef>

// Problem constants
#define BROWS 16384
#define INDIM 1024
#define HID   4096
#define ODIM  384
#define NGRP  6
#define POOL  64
#define TOPK  2

// ---------------- scratch (device globals; no allocation allowed) ----------------
// All operands stored as interleaved float2 {hi, lo} tf32 pairs.
__device__ __align__(16) float2 g_q2[(size_t)BROWS * INDIM];   // 134 MB
__device__ __align__(16) float2 g_w1s[(size_t)INDIM * HID];    //  34 MB
__device__ __align__(16) float2 g_w2s[(size_t)HID * HID];      // 134 MB
__device__ __align__(16) float2 g_w3s[(size_t)HID * ODIM];     //  13 MB
__device__ __align__(16) float2 g_h1[(size_t)BROWS * HID];     // 537 MB
__device__ __align__(16) float2 g_h2[(size_t)BROWS * HID];     // 537 MB

// ---------------- helpers ----------------
__device__ __forceinline__ float tf32r(float x) {
    uint32_t u;
    asm("cvt.rna.tf32.f32 %0, %1;" : "=r"(u) : "f"(x));
    return __uint_as_float(u);
}
__device__ __forceinline__ float gelu_f(float x) {
    float t = tanhf(0.7978845608028654f * (x + 0.044715f * x * x * x));
    return 0.5f * x * (1.0f + t);
}
__device__ __forceinline__ float sig2_f(float x) {
    return 2.0f / (1.0f + expf(-x));
}

#define CP_ASYNC16(dst, src) \
    asm volatile("cp.async.cg.shared.global [%0], [%1], 16;\n" :: "r"(dst), "l"(src) : "memory")
#define CP_COMMIT() asm volatile("cp.async.commit_group;\n" ::: "memory")
#define CP_WAIT2()  asm volatile("cp.async.wait_group 2;\n" ::: "memory")
#define CP_WAIT1()  asm volatile("cp.async.wait_group 1;\n" ::: "memory")
#define CP_WAIT0()  asm volatile("cp.async.wait_group 0;\n" ::: "memory")

#define MMA_TF32(C0, C1, C2, C3, A0, A1, A2, A3, B0, B1) \
    asm volatile( \
        "mma.sync.aligned.m16n8k8.row.col.f32.tf32.tf32.f32 " \
        "{%0,%1,%2,%3}, {%4,%5,%6,%7}, {%8,%9}, {%0,%1,%2,%3};\n" \
        : "+f"(C0), "+f"(C1), "+f"(C2), "+f"(C3) \
        : "r"(A0), "r"(A1), "r"(A2), "r"(A3), "r"(B0), "r"(B1))

// ---------------- GEMM smem layout: 4 stages, BK=16 ----------------
// A stage: 128 rows x 20 float2 (16 data + 4 pad) = 20480 B
// B stage:  16 rows x 132 float2 (128 data + 4 pad) = 16896 B
#define AP2   20
#define BP2   132
#define ASTG  20480
#define STG   37376
#define GSMEM (4 * STG)   // 149504 B

// ---------------- 3xTF32 GEMM on prepass-split operands ----------------
// A: [M][K] float2 {hi,lo}; B: [K][N] float2 {hi,lo}.
// cc += ah*bh ; s2 += ah*bl + al*bh  (separate accumulator preserves precision)
// EPI==0: gelu, output interleaved float2 {tf32 hi, lo}. EPI==1: 2*sigmoid, fp32.
template <int EPI>
__global__ __launch_bounds__(256, 1) void gemm_s(
    const float2* __restrict__ A, const float2* __restrict__ B,
    const float* __restrict__ bias, void* __restrict__ Cout,
    int N, int K, int nk)
{
    extern __shared__ char sm[];
    const uint32_t sbase = (uint32_t)__cvta_generic_to_shared(sm);

    const int tid  = threadIdx.x;
    const int lane = tid & 31;
    const int warp = tid >> 5;
    const int wm = warp & 1;      // 2 warp rows (64 each)
    const int wn = warp >> 1;     // 4 warp cols (32 each)
    const int gid = lane >> 2;    // 0..7
    const int tq  = lane & 3;     // 0..3

    const int m0 = blockIdx.y * 128;
    const int n0 = blockIdx.x * 128;

    auto load_stage = [&](int kt, int s) {
        const uint32_t abase = sbase + (uint32_t)s * STG;
        const uint32_t bbase = abase + ASTG;
#pragma unroll
        for (int p = 0; p < 4; p++) {
            const int c = p * 256 + tid;   // 0..1023 (256 threads x 4 passes)
            {   // A: 128 rows x 8 chunks of 16B = 1024 chunks
                const int row = c >> 3, kc = c & 7;
                const float2* g = A + (size_t)(m0 + row) * K + kt * 16 + kc * 2;
                CP_ASYNC16(abase + (uint32_t)(row * 160 + kc * 16), g);
            }
            {   // B: 16 rows x 64 chunks of 16B = 1024 chunks
                const int row = c >> 6, nc = c & 63;
                const float2* g = B + (size_t)(kt * 16 + row) * N + n0 + nc * 2;
                CP_ASYNC16(bbase + (uint32_t)(row * 1056 + nc * 16), g);
            }
        }
        CP_COMMIT();
    };

    float cc[4][4][4];   // hi*hi
    float s2[4][4][4];   // cross terms
#pragma unroll
    for (int a = 0; a < 4; a++)
#pragma unroll
        for (int b = 0; b < 4; b++)
#pragma unroll
            for (int d = 0; d < 4; d++) { cc[a][b][d] = 0.0f; s2[a][b][d] = 0.0f; }

    // prologue: 3 stages in flight
    load_stage(0, 0);
    load_stage(1, 1);
    load_stage(2, 2);

    for (int kt = 0; kt < nk; kt++) {
        const int rem = nk - 1 - kt;
        if (rem >= 2) { CP_WAIT2(); } else if (rem == 1) { CP_WAIT1(); } else { CP_WAIT0(); }
        __syncthreads();

        const int s = kt & 3;
        const float2* As = (const float2*)(sm + (size_t)s * STG);
        const float2* Bs = (const float2*)(sm + (size_t)s * STG + ASTG);

#pragma unroll
        for (int ks = 0; ks < 2; ks++) {
            const int k0 = ks * 8 + tq;
            uint32_t ah[4][4], al[4][4], bh[4][2], bl[4][2];
#pragma unroll
            for (int mi = 0; mi < 4; mi++) {
                const int r = wm * 64 + mi * 16 + gid;
                const int ia = r * AP2 + k0;
                const float2 f0 = As[ia];
                const float2 f1 = As[ia + 8 * AP2];
                const float2 f2 = As[ia + 4];
                const float2 f3 = As[ia + 8 * AP2 + 4];
                ah[mi][0] = __float_as_uint(f0.x); al[mi][0] = __float_as_uint(f0.y);
                ah[mi][1] = __float_as_uint(f1.x); al[mi][1] = __float_as_uint(f1.y);
                ah[mi][2] = __float_as_uint(f2.x); al[mi][2] = __float_as_uint(f2.y);
                ah[mi][3] = __float_as_uint(f3.x); al[mi][3] = __float_as_uint(f3.y);
            }
#pragma unroll
            for (int ni = 0; ni < 4; ni++) {
                const int cN = wn * 32 + ni * 8 + gid;
                const int ib = k0 * BP2 + cN;
                const float2 f0 = Bs[ib];
                const float2 f1 = Bs[ib + 4 * BP2];
                bh[ni][0] = __float_as_uint(f0.x); bl[ni][0] = __float_as_uint(f0.y);
                bh[ni][1] = __float_as_uint(f1.x); bl[ni][1] = __float_as_uint(f1.y);
            }
#pragma unroll
            for (int mi = 0; mi < 4; mi++)
#pragma unroll
                for (int ni = 0; ni < 4; ni++) {
                    MMA_TF32(cc[mi][ni][0], cc[mi][ni][1], cc[mi][ni][2], cc[mi][ni][3],
                             ah[mi][0], ah[mi][1], ah[mi][2], ah[mi][3],
                             bh[ni][0], bh[ni][1]);
                    MMA_TF32(s2[mi][ni][0], s2[mi][ni][1], s2[mi][ni][2], s2[mi][ni][3],
                             ah[mi][0], ah[mi][1], ah[mi][2], ah[mi][3],
                             bl[ni][0], bl[ni][1]);
                    MMA_TF32(s2[mi][ni][0], s2[mi][ni][1], s2[mi][ni][2], s2[mi][ni][3],
                             al[mi][0], al[mi][1], al[mi][2], al[mi][3],
                             bh[ni][0], bh[ni][1]);
                }
        }

        if (kt + 3 < nk) load_stage(kt + 3, (kt + 3) & 3);
    }

    // ---- epilogue: combine + bias + activation (fp32), direct global stores ----
#pragma unroll
    for (int mi = 0; mi < 4; mi++) {
        const int row0 = m0 + wm * 64 + mi * 16 + gid;
#pragma unroll
        for (int ni = 0; ni < 4; ni++) {
            const int col = n0 + wn * 32 + ni * 8 + tq * 2;
            const float bb0 = __ldg(bias + col);
            const float bb1 = __ldg(bias + col + 1);
            float v00 = cc[mi][ni][0] + s2[mi][ni][0] + bb0;
            float v01 = cc[mi][ni][1] + s2[mi][ni][1] + bb1;
            float v10 = cc[mi][ni][2] + s2[mi][ni][2] + bb0;
            float v11 = cc[mi][ni][3] + s2[mi][ni][3] + bb1;
            if (EPI == 0) {
                float2* C2 = (float2*)Cout;
                const float g00 = gelu_f(v00), g01 = gelu_f(v01);
                const float g10 = gelu_f(v10), g11 = gelu_f(v11);
                const float h00 = tf32r(g00), h01 = tf32r(g01);
                const float h10 = tf32r(g10), h11 = tf32r(g11);
                *(float4*)(C2 + (size_t)row0 * N + col) =
                    make_float4(h00, tf32r(g00 - h00), h01, tf32r(g01 - h01));
                *(float4*)(C2 + (size_t)(row0 + 8) * N + col) =
                    make_float4(h10, tf32r(g10 - h10), h11, tf32r(g11 - h11));
            } else {
                float* C = (float*)Cout;
                *(float2*)(C + (size_t)row0 * N + col) =
                    make_float2(sig2_f(v00), sig2_f(v01));
                *(float2*)(C + (size_t)(row0 + 8) * N + col) =
                    make_float2(sig2_f(v10), sig2_f(v11));
            }
        }
    }
}

// ---------------- prepass: fp32 -> interleaved (hi, lo) tf32 float2 ----------------
__global__ void split2_kernel(const float4* __restrict__ in, float4* __restrict__ out, int n4) {
    int i = blockIdx.x * blockDim.x + threadIdx.x;
    if (i < n4) {
        float4 v = in[i];
        float h0 = tf32r(v.x), h1 = tf32r(v.y), h2 = tf32r(v.z), h3 = tf32r(v.w);
        out[2 * i]     = make_float4(h0, tf32r(v.x - h0), h1, tf32r(v.y - h1));
        out[2 * i + 1] = make_float4(h2, tf32r(v.z - h2), h3, tf32r(v.w - h3));
    }
}

// ---------------- per-group top-2 (stable, descending — matches jax.lax.top_k) ----------------
__global__ void topk_kernel(const float* __restrict__ coeff,
                            float* __restrict__ tv, float* __restrict__ ti) {
    int g = blockIdx.x * blockDim.x + threadIdx.x;
    if (g >= BROWS * NGRP) return;
    const int row = g / NGRP;
    const int grp = g - row * NGRP;
    const float* p = coeff + (size_t)row * ODIM + grp * POOL;
    float v1 = -1e30f, v2 = -1e30f;
    int i1 = 0, i2 = 0;
#pragma unroll 8
    for (int i = 0; i < POOL; i++) {
        float v = p[i];
        if (v > v1) { v2 = v1; i2 = i1; v1 = v; i1 = i; }
        else if (v > v2) { v2 = v; i2 = i; }
    }
    const size_t o = (size_t)row * (NGRP * TOPK) + grp * TOPK;
    tv[o] = v1; tv[o + 1] = v2;
    ti[o] = (float)i1; ti[o + 1] = (float)i2;
}

// ---------------- launch ----------------
extern "C" void kernel_launch(void* const* d_in, const int* in_sizes, int n_in,
                              void* d_out, int out_size)
{
    const float* q  = (const float*)d_in[0];
    const float* W1 = (const float*)d_in[1];
    const float* b1 = (const float*)d_in[2];
    const float* W2 = (const float*)d_in[3];
    const float* b2 = (const float*)d_in[4];
    const float* W3 = (const float*)d_in[5];
    const float* b3 = (const float*)d_in[6];
    float* out = (float*)d_out;

    static bool configured = false;
    static float2 *q2, *w1s, *w2s, *w3s, *h1, *h2;
    if (!configured) {
        cudaGetSymbolAddress((void**)&q2,  g_q2);
        cudaGetSymbolAddress((void**)&w1s, g_w1s);
        cudaGetSymbolAddress((void**)&w2s, g_w2s);
        cudaGetSymbolAddress((void**)&w3s, g_w3s);
        cudaGetSymbolAddress((void**)&h1,  g_h1);
        cudaGetSymbolAddress((void**)&h2,  g_h2);
        cudaFuncSetAttribute(gemm_s<0>, cudaFuncAttributeMaxDynamicSharedMemorySize, GSMEM);
        cudaFuncSetAttribute(gemm_s<1>, cudaFuncAttributeMaxDynamicSharedMemorySize, GSMEM);
        configured = true;
    }

    // 1) split prepasses (weights + query)
    {
        int n4;
        n4 = (BROWS * INDIM) / 4;
        split2_kernel<<<(n4 + 255) / 256, 256>>>((const float4*)q,  (float4*)q2,  n4);
        n4 = (INDIM * HID) / 4;
        split2_kernel<<<(n4 + 255) / 256, 256>>>((const float4*)W1, (float4*)w1s, n4);
        n4 = (HID * HID) / 4;
        split2_kernel<<<(n4 + 255) / 256, 256>>>((const float4*)W2, (float4*)w2s, n4);
        n4 = (HID * ODIM) / 4;
        split2_kernel<<<(n4 + 255) / 256, 256>>>((const float4*)W3, (float4*)w3s, n4);
    }

    // 2) three GEMMs (fused split epilogues on 1 & 2)
    dim3 blk(256);
    gemm_s<0><<<dim3(HID / 128, BROWS / 128), blk, GSMEM>>>(q2, w1s, b1, h1, HID, INDIM, INDIM / 16);
    gemm_s<0><<<dim3(HID / 128, BROWS / 128), blk, GSMEM>>>(h1, w2s, b2, h2, HID, HID, HID / 16);
    gemm_s<1><<<dim3(ODIM / 128, BROWS / 128), blk, GSMEM>>>(h2, w3s, b3, out, ODIM, HID, HID / 16);

    // 3) top-2 per group; outputs concatenated: coeff | topk_coeff | topk_idx(as float)
    float* tv = out + (size_t)BROWS * ODIM;
    float* ti = tv + (size_t)BROWS * NGRP * TOPK;
    topk_kernel<<<(BROWS * NGRP + 255) / 256, 256>>>(out, tv, ti);
}

// round 11
// speedup vs baseline: 2.2338x; 2.2338x over previous
#include <cuda_runtime.h>
#include <cuda_fp16.h>
#include <cstdint>
#include <cstddef>

// Problem constants
#define BROWS 16384
#define INDIM 1024
#define HID   4096
#define ODIM  384
#define NGRP  6
#define POOL  64
#define TOPK  2

#define RSCALE   2048.0f          // 2^11: residual pre-scale
#define RSCALE_I 0.00048828125f   // 2^-11

// ---------------- scratch (device globals; no allocation allowed) ----------------
// hi/lo fp16 planes. Weights stored transposed [N][K] for .col B fragments.
__device__ __align__(16) __half g_qh[(size_t)BROWS * INDIM];
__device__ __align__(16) __half g_ql[(size_t)BROWS * INDIM];
__device__ __align__(16) __half g_w1h[(size_t)HID * INDIM];
__device__ __align__(16) __half g_w1l[(size_t)HID * INDIM];
__device__ __align__(16) __half g_w2h[(size_t)HID * HID];
__device__ __align__(16) __half g_w2l[(size_t)HID * HID];
__device__ __align__(16) __half g_w3h[(size_t)ODIM * HID];
__device__ __align__(16) __half g_w3l[(size_t)ODIM * HID];
__device__ __align__(16) __half g_h1h[(size_t)BROWS * HID];
__device__ __align__(16) __half g_h1l[(size_t)BROWS * HID];
__device__ __align__(16) __half g_h2h[(size_t)BROWS * HID];
__device__ __align__(16) __half g_h2l[(size_t)BROWS * HID];

// ---------------- helpers ----------------
__device__ __forceinline__ float gelu_f(float x) {
    float t = tanhf(0.7978845608028654f * (x + 0.044715f * x * x * x));
    return 0.5f * x * (1.0f + t);
}
__device__ __forceinline__ float sig2_f(float x) {
    return 2.0f / (1.0f + expf(-x));
}

#define CP_ASYNC16(dst, src) \
    asm volatile("cp.async.cg.shared.global [%0], [%1], 16;\n" :: "r"(dst), "l"(src) : "memory")
#define CP_COMMIT() asm volatile("cp.async.commit_group;\n" ::: "memory")
#define CP_WAIT2()  asm volatile("cp.async.wait_group 2;\n" ::: "memory")
#define CP_WAIT1()  asm volatile("cp.async.wait_group 1;\n" ::: "memory")
#define CP_WAIT0()  asm volatile("cp.async.wait_group 0;\n" ::: "memory")

#define MMA_F16(C0, C1, C2, C3, A0, A1, A2, A3, B0, B1) \
    asm volatile( \
        "mma.sync.aligned.m16n8k16.row.col.f32.f16.f16.f32 " \
        "{%0,%1,%2,%3}, {%4,%5,%6,%7}, {%8,%9}, {%0,%1,%2,%3};\n" \
        : "+f"(C0), "+f"(C1), "+f"(C2), "+f"(C3) \
        : "r"(A0), "r"(A1), "r"(A2), "r"(A3), "r"(B0), "r"(B1))

// ---------------- smem: 4 stages, BK=32, pitch 80B (40 half) ----------------
// stage: Ah[128][40] | Al | Bh[128][40] | Bl  (each 10240 B) = 40960 B
#define PB    80          // row pitch bytes
#define PLANE 10240
#define STG   40960
#define GSMEM (4 * STG)   // 163840 B

// ---------------- 3-product fp16-split GEMM ----------------
// A planes: [M][K] fp16 (hi, lo*2^11). B planes: Wt [N][K] fp16.
// cc += ah*bh ; s2 += ah*bl + al*bh ; result = cc + s2*2^-11 + bias
// EPI==0: gelu -> write hi/lo fp16 planes. EPI==1: 2*sigmoid -> fp32.
template <int EPI>
__global__ __launch_bounds__(256, 1) void gemm_h(
    const __half* __restrict__ Ah_g, const __half* __restrict__ Al_g,
    const __half* __restrict__ Bh_g, const __half* __restrict__ Bl_g,
    const float* __restrict__ bias,
    __half* __restrict__ Ohi, __half* __restrict__ Olo, float* __restrict__ Oc,
    int N, int K, int nk)
{
    extern __shared__ char sm[];
    const uint32_t sbase = (uint32_t)__cvta_generic_to_shared(sm);

    const int tid  = threadIdx.x;
    const int lane = tid & 31;
    const int warp = tid >> 5;
    const int wm = warp & 1;      // 2 warp rows (64 each)
    const int wn = warp >> 1;     // 4 warp cols (32 each)
    const int gid = lane >> 2;    // 0..7
    const int tq  = lane & 3;     // 0..3

    const int m0 = blockIdx.y * 128;
    const int n0 = blockIdx.x * 128;

    auto load_stage = [&](int kt, int s) {
        const uint32_t st = sbase + (uint32_t)s * STG;
#pragma unroll
        for (int p = 0; p < 2; p++) {
            const int c = p * 256 + tid;        // 0..511
            const int row = c >> 2, kc = c & 3; // 128 rows x 4 chunks of 16B (8 half)
            const uint32_t off = (uint32_t)(row * PB + kc * 16);
            const size_t ga = (size_t)(m0 + row) * K + kt * 32 + kc * 8;
            const size_t gb = (size_t)(n0 + row) * K + kt * 32 + kc * 8;
            CP_ASYNC16(st + 0 * PLANE + off, Ah_g + ga);
            CP_ASYNC16(st + 1 * PLANE + off, Al_g + ga);
            CP_ASYNC16(st + 2 * PLANE + off, Bh_g + gb);
            CP_ASYNC16(st + 3 * PLANE + off, Bl_g + gb);
        }
        CP_COMMIT();
    };

    float cc[4][4][4];   // ah*bh
    float s2[4][4][4];   // ah*bl + al*bh  (pre-scaled by 2^11)
#pragma unroll
    for (int a = 0; a < 4; a++)
#pragma unroll
        for (int b = 0; b < 4; b++)
#pragma unroll
            for (int d = 0; d < 4; d++) { cc[a][b][d] = 0.0f; s2[a][b][d] = 0.0f; }

    load_stage(0, 0);
    load_stage(1, 1);
    load_stage(2, 2);

    for (int kt = 0; kt < nk; kt++) {
        const int rem = nk - 1 - kt;
        if (rem >= 2) { CP_WAIT2(); } else if (rem == 1) { CP_WAIT1(); } else { CP_WAIT0(); }
        __syncthreads();

        const char* st = sm + (size_t)(kt & 3) * STG;
        const char* Ah_s = st;
        const char* Al_s = st + PLANE;
        const char* Bh_s = st + 2 * PLANE;
        const char* Bl_s = st + 3 * PLANE;

#pragma unroll
        for (int ks = 0; ks < 2; ks++) {
            const int kb = ks * 32 + tq * 4;   // byte offset of this thread's k-pair
            uint32_t ah[4][4], al[4][4], bh[4][2], bl[4][2];
#pragma unroll
            for (int mi = 0; mi < 4; mi++) {
                const int r = wm * 64 + mi * 16 + gid;
                const char* p0 = Ah_s + r * PB + kb;
                const char* p1 = Al_s + r * PB + kb;
                ah[mi][0] = *(const uint32_t*)(p0);
                ah[mi][1] = *(const uint32_t*)(p0 + 8 * PB);
                ah[mi][2] = *(const uint32_t*)(p0 + 16);
                ah[mi][3] = *(const uint32_t*)(p0 + 8 * PB + 16);
                al[mi][0] = *(const uint32_t*)(p1);
                al[mi][1] = *(const uint32_t*)(p1 + 8 * PB);
                al[mi][2] = *(const uint32_t*)(p1 + 16);
                al[mi][3] = *(const uint32_t*)(p1 + 8 * PB + 16);
            }
#pragma unroll
            for (int ni = 0; ni < 4; ni++) {
                const int nrow = wn * 32 + ni * 8 + gid;
                const char* p0 = Bh_s + nrow * PB + kb;
                const char* p1 = Bl_s + nrow * PB + kb;
                bh[ni][0] = *(const uint32_t*)(p0);
                bh[ni][1] = *(const uint32_t*)(p0 + 16);
                bl[ni][0] = *(const uint32_t*)(p1);
                bl[ni][1] = *(const uint32_t*)(p1 + 16);
            }
#pragma unroll
            for (int mi = 0; mi < 4; mi++)
#pragma unroll
                for (int ni = 0; ni < 4; ni++) {
                    MMA_F16(cc[mi][ni][0], cc[mi][ni][1], cc[mi][ni][2], cc[mi][ni][3],
                            ah[mi][0], ah[mi][1], ah[mi][2], ah[mi][3],
                            bh[ni][0], bh[ni][1]);
                    MMA_F16(s2[mi][ni][0], s2[mi][ni][1], s2[mi][ni][2], s2[mi][ni][3],
                            ah[mi][0], ah[mi][1], ah[mi][2], ah[mi][3],
                            bl[ni][0], bl[ni][1]);
                    MMA_F16(s2[mi][ni][0], s2[mi][ni][1], s2[mi][ni][2], s2[mi][ni][3],
                            al[mi][0], al[mi][1], al[mi][2], al[mi][3],
                            bh[ni][0], bh[ni][1]);
                }
        }

        if (kt + 3 < nk) load_stage(kt + 3, (kt + 3) & 3);
    }

    // ---- epilogue ----
#pragma unroll
    for (int mi = 0; mi < 4; mi++) {
        const int row0 = m0 + wm * 64 + mi * 16 + gid;
#pragma unroll
        for (int ni = 0; ni < 4; ni++) {
            const int col = n0 + wn * 32 + ni * 8 + tq * 2;
            const float bb0 = __ldg(bias + col);
            const float bb1 = __ldg(bias + col + 1);
            float v00 = fmaf(s2[mi][ni][0], RSCALE_I, cc[mi][ni][0]) + bb0;
            float v01 = fmaf(s2[mi][ni][1], RSCALE_I, cc[mi][ni][1]) + bb1;
            float v10 = fmaf(s2[mi][ni][2], RSCALE_I, cc[mi][ni][2]) + bb0;
            float v11 = fmaf(s2[mi][ni][3], RSCALE_I, cc[mi][ni][3]) + bb1;
            if (EPI == 0) {
                const float g00 = gelu_f(v00), g01 = gelu_f(v01);
                const float g10 = gelu_f(v10), g11 = gelu_f(v11);
                const __half h00 = __float2half_rn(g00), h01 = __float2half_rn(g01);
                const __half h10 = __float2half_rn(g10), h11 = __float2half_rn(g11);
                __half2 hl0; hl0.x = h00; hl0.y = h01;
                __half2 hl1; hl1.x = h10; hl1.y = h11;
                *(__half2*)(Ohi + (size_t)row0 * N + col)       = hl0;
                *(__half2*)(Ohi + (size_t)(row0 + 8) * N + col) = hl1;
                __half2 ll0, ll1;
                ll0.x = __float2half_rn((g00 - __half2float(h00)) * RSCALE);
                ll0.y = __float2half_rn((g01 - __half2float(h01)) * RSCALE);
                ll1.x = __float2half_rn((g10 - __half2float(h10)) * RSCALE);
                ll1.y = __float2half_rn((g11 - __half2float(h11)) * RSCALE);
                *(__half2*)(Olo + (size_t)row0 * N + col)       = ll0;
                *(__half2*)(Olo + (size_t)(row0 + 8) * N + col) = ll1;
            } else {
                *(float2*)(Oc + (size_t)row0 * N + col) =
                    make_float2(sig2_f(v00), sig2_f(v01));
                *(float2*)(Oc + (size_t)(row0 + 8) * N + col) =
                    make_float2(sig2_f(v10), sig2_f(v11));
            }
        }
    }
}

// ---------------- prepass: fp32 -> hi/lo fp16 planes (lo pre-scaled 2^11) ----------------
__global__ void split16_kernel(const float4* __restrict__ in,
                               __half* __restrict__ hi, __half* __restrict__ lo, int n4) {
    int i = blockIdx.x * blockDim.x + threadIdx.x;
    if (i < n4) {
        float4 v = in[i];
        __half h0 = __float2half_rn(v.x), h1 = __float2half_rn(v.y);
        __half h2 = __float2half_rn(v.z), h3 = __float2half_rn(v.w);
        __half2 ha; ha.x = h0; ha.y = h1;
        __half2 hb; hb.x = h2; hb.y = h3;
        *(__half2*)(hi + 4 * (size_t)i)     = ha;
        *(__half2*)(hi + 4 * (size_t)i + 2) = hb;
        __half2 la, lb;
        la.x = __float2half_rn((v.x - __half2float(h0)) * RSCALE);
        la.y = __float2half_rn((v.y - __half2float(h1)) * RSCALE);
        lb.x = __float2half_rn((v.z - __half2float(h2)) * RSCALE);
        lb.y = __float2half_rn((v.w - __half2float(h3)) * RSCALE);
        *(__half2*)(lo + 4 * (size_t)i)     = la;
        *(__half2*)(lo + 4 * (size_t)i + 2) = lb;
    }
}

// ---------------- prepass: W[K,N] fp32 -> Wt hi/lo [N][K] fp16 ----------------
__global__ void tsplit16_kernel(const float* __restrict__ W,
                                __half* __restrict__ hi, __half* __restrict__ lo,
                                int K, int N) {
    __shared__ float t[32][33];
    const int nb = blockIdx.x * 32, kb = blockIdx.y * 32;
    const int tx = threadIdx.x, ty = threadIdx.y;
#pragma unroll
    for (int r = ty; r < 32; r += 8)
        t[r][tx] = W[(size_t)(kb + r) * N + nb + tx];
    __syncthreads();
#pragma unroll
    for (int r = ty; r < 32; r += 8) {
        const float v = t[tx][r];   // = W[kb+tx][nb+r]
        const __half h = __float2half_rn(v);
        hi[(size_t)(nb + r) * K + kb + tx] = h;
        lo[(size_t)(nb + r) * K + kb + tx] =
            __float2half_rn((v - __half2float(h)) * RSCALE);
    }
}

// ---------------- per-group top-2 (stable, descending — matches jax.lax.top_k) ----------------
__global__ void topk_kernel(const float* __restrict__ coeff,
                            float* __restrict__ tv, float* __restrict__ ti) {
    int g = blockIdx.x * blockDim.x + threadIdx.x;
    if (g >= BROWS * NGRP) return;
    const int row = g / NGRP;
    const int grp = g - row * NGRP;
    const float* p = coeff + (size_t)row * ODIM + grp * POOL;
    float v1 = -1e30f, v2 = -1e30f;
    int i1 = 0, i2 = 0;
#pragma unroll 8
    for (int i = 0; i < POOL; i++) {
        float v = p[i];
        if (v > v1) { v2 = v1; i2 = i1; v1 = v; i1 = i; }
        else if (v > v2) { v2 = v; i2 = i; }
    }
    const size_t o = (size_t)row * (NGRP * TOPK) + grp * TOPK;
    tv[o] = v1; tv[o + 1] = v2;
    ti[o] = (float)i1; ti[o + 1] = (float)i2;
}

// ---------------- launch ----------------
extern "C" void kernel_launch(void* const* d_in, const int* in_sizes, int n_in,
                              void* d_out, int out_size)
{
    const float* q  = (const float*)d_in[0];
    const float* W1 = (const float*)d_in[1];
    const float* b1 = (const float*)d_in[2];
    const float* W2 = (const float*)d_in[3];
    const float* b2 = (const float*)d_in[4];
    const float* W3 = (const float*)d_in[5];
    const float* b3 = (const float*)d_in[6];
    float* out = (float*)d_out;

    static bool configured = false;
    static __half *qh, *ql, *w1h, *w1l, *w2h, *w2l, *w3h, *w3l, *h1h, *h1l, *h2h, *h2l;
    if (!configured) {
        cudaGetSymbolAddress((void**)&qh,  g_qh);  cudaGetSymbolAddress((void**)&ql,  g_ql);
        cudaGetSymbolAddress((void**)&w1h, g_w1h); cudaGetSymbolAddress((void**)&w1l, g_w1l);
        cudaGetSymbolAddress((void**)&w2h, g_w2h); cudaGetSymbolAddress((void**)&w2l, g_w2l);
        cudaGetSymbolAddress((void**)&w3h, g_w3h); cudaGetSymbolAddress((void**)&w3l, g_w3l);
        cudaGetSymbolAddress((void**)&h1h, g_h1h); cudaGetSymbolAddress((void**)&h1l, g_h1l);
        cudaGetSymbolAddress((void**)&h2h, g_h2h); cudaGetSymbolAddress((void**)&h2l, g_h2l);
        cudaFuncSetAttribute(gemm_h<0>, cudaFuncAttributeMaxDynamicSharedMemorySize, GSMEM);
        cudaFuncSetAttribute(gemm_h<1>, cudaFuncAttributeMaxDynamicSharedMemorySize, GSMEM);
        configured = true;
    }

    // 1) prepasses: query split + weight transpose-splits
    {
        int n4 = (BROWS * INDIM) / 4;
        split16_kernel<<<(n4 + 255) / 256, 256>>>((const float4*)q, qh, ql, n4);
    }
    dim3 tb(32, 8);
    tsplit16_kernel<<<dim3(HID / 32, INDIM / 32), tb>>>(W1, w1h, w1l, INDIM, HID);
    tsplit16_kernel<<<dim3(HID / 32, HID / 32),  tb>>>(W2, w2h, w2l, HID,  HID);
    tsplit16_kernel<<<dim3(ODIM / 32, HID / 32), tb>>>(W3, w3h, w3l, HID,  ODIM);

    // 2) three GEMMs
    dim3 blk(256);
    gemm_h<0><<<dim3(HID / 128, BROWS / 128), blk, GSMEM>>>(
        qh, ql, w1h, w1l, b1, h1h, h1l, nullptr, HID, INDIM, INDIM / 32);
    gemm_h<0><<<dim3(HID / 128, BROWS / 128), blk, GSMEM>>>(
        h1h, h1l, w2h, w2l, b2, h2h, h2l, nullptr, HID, HID, HID / 32);
    gemm_h<1><<<dim3(ODIM / 128, BROWS / 128), blk, GSMEM>>>(
        h2h, h2l, w3h, w3l, b3, nullptr, nullptr, out, ODIM, HID, HID / 32);

    // 3) top-2 per group; outputs concatenated: coeff | topk_coeff | topk_idx(as float)
    float* tv = out + (size_t)BROWS * ODIM;
    float* ti = tv + (size_t)BROWS * NGRP * TOPK;
    topk_kernel<<<(BROWS * NGRP + 255) / 256, 256>>>(out, tv, ti);
}

// round 12
// speedup vs baseline: 2.2392x; 1.0024x over previous
#include <cuda_runtime.h>
#include <cuda_fp16.h>
#include <cstdint>
#include <cstddef>

// Problem constants
#define BROWS 16384
#define INDIM 1024
#define HID   4096
#define ODIM  384
#define NGRP  6
#define POOL  64
#define TOPK  2

#define RSCALE   2048.0f          // 2^11: residual pre-scale
#define RSCALE_I 0.00048828125f   // 2^-11

// ---------------- scratch (device globals; no allocation allowed) ----------------
// hi/lo fp16 planes. Weights stored transposed [N][K] for .col B fragments.
__device__ __align__(16) __half g_qh[(size_t)BROWS * INDIM];
__device__ __align__(16) __half g_ql[(size_t)BROWS * INDIM];
__device__ __align__(16) __half g_w1h[(size_t)HID * INDIM];
__device__ __align__(16) __half g_w1l[(size_t)HID * INDIM];
__device__ __align__(16) __half g_w2h[(size_t)HID * HID];
__device__ __align__(16) __half g_w2l[(size_t)HID * HID];
__device__ __align__(16) __half g_w3h[(size_t)ODIM * HID];
__device__ __align__(16) __half g_w3l[(size_t)ODIM * HID];
__device__ __align__(16) __half g_h1h[(size_t)BROWS * HID];
__device__ __align__(16) __half g_h1l[(size_t)BROWS * HID];
__device__ __align__(16) __half g_h2h[(size_t)BROWS * HID];
__device__ __align__(16) __half g_h2l[(size_t)BROWS * HID];

// ---------------- helpers ----------------
__device__ __forceinline__ float gelu_f(float x) {
    float t = tanhf(0.7978845608028654f * (x + 0.044715f * x * x * x));
    return 0.5f * x * (1.0f + t);
}
__device__ __forceinline__ float sig2_f(float x) {
    return 2.0f / (1.0f + expf(-x));
}

#define CP_ASYNC16(dst, src) \
    asm volatile("cp.async.cg.shared.global [%0], [%1], 16;\n" :: "r"(dst), "l"(src) : "memory")
#define CP_COMMIT() asm volatile("cp.async.commit_group;\n" ::: "memory")
#define CP_WAIT2()  asm volatile("cp.async.wait_group 2;\n" ::: "memory")
#define CP_WAIT1()  asm volatile("cp.async.wait_group 1;\n" ::: "memory")
#define CP_WAIT0()  asm volatile("cp.async.wait_group 0;\n" ::: "memory")

#define MMA_F16(C0, C1, C2, C3, A0, A1, A2, A3, B0, B1) \
    asm volatile( \
        "mma.sync.aligned.m16n8k16.row.col.f32.f16.f16.f32 " \
        "{%0,%1,%2,%3}, {%4,%5,%6,%7}, {%8,%9}, {%0,%1,%2,%3};\n" \
        : "+f"(C0), "+f"(C1), "+f"(C2), "+f"(C3) \
        : "r"(A0), "r"(A1), "r"(A2), "r"(A3), "r"(B0), "r"(B1))

// ---------------- smem: 4 stages, BK=32, pitch 80B (40 half) ----------------
// stage: Ah[128][40] | Al | Bh[128][40] | Bl  (each 10240 B) = 40960 B
#define PB    80          // row pitch bytes
#define PLANE 10240
#define STG   40960
#define GSMEM (4 * STG)   // 163840 B  (also covers 128x129 f32 topk stage = 66048 B)

// ---------------- 3-product fp16-split GEMM ----------------
// A planes: [M][K] fp16 (hi, lo*2^11). B planes: Wt [N][K] fp16.
// cc += ah*bh ; s2 += ah*bl + al*bh ; result = cc + s2*2^-11 + bias
// EPI==0: gelu -> write hi/lo fp16 planes.
// EPI==1: 2*sigmoid -> fp32 coeff + in-CTA per-group top-2 (tv/ti).
template <int EPI>
__global__ __launch_bounds__(256, 1) void gemm_h(
    const __half* __restrict__ Ah_g, const __half* __restrict__ Al_g,
    const __half* __restrict__ Bh_g, const __half* __restrict__ Bl_g,
    const float* __restrict__ bias,
    __half* __restrict__ Ohi, __half* __restrict__ Olo, float* __restrict__ Oc,
    float* __restrict__ Tv, float* __restrict__ Ti,
    int N, int K, int nk)
{
    extern __shared__ char sm[];
    const uint32_t sbase = (uint32_t)__cvta_generic_to_shared(sm);

    const int tid  = threadIdx.x;
    const int lane = tid & 31;
    const int warp = tid >> 5;
    const int wm = warp & 1;      // 2 warp rows (64 each)
    const int wn = warp >> 1;     // 4 warp cols (32 each)
    const int gid = lane >> 2;    // 0..7
    const int tq  = lane & 3;     // 0..3

    const int m0 = blockIdx.y * 128;
    const int n0 = blockIdx.x * 128;

    auto load_stage = [&](int kt, int s) {
        const uint32_t st = sbase + (uint32_t)s * STG;
#pragma unroll
        for (int p = 0; p < 2; p++) {
            const int c = p * 256 + tid;        // 0..511
            const int row = c >> 2, kc = c & 3; // 128 rows x 4 chunks of 16B (8 half)
            const uint32_t off = (uint32_t)(row * PB + kc * 16);
            const size_t ga = (size_t)(m0 + row) * K + kt * 32 + kc * 8;
            const size_t gb = (size_t)(n0 + row) * K + kt * 32 + kc * 8;
            CP_ASYNC16(st + 0 * PLANE + off, Ah_g + ga);
            CP_ASYNC16(st + 1 * PLANE + off, Al_g + ga);
            CP_ASYNC16(st + 2 * PLANE + off, Bh_g + gb);
            CP_ASYNC16(st + 3 * PLANE + off, Bl_g + gb);
        }
        CP_COMMIT();
    };

    float cc[4][4][4];   // ah*bh
    float s2[4][4][4];   // ah*bl + al*bh  (pre-scaled by 2^11)
#pragma unroll
    for (int a = 0; a < 4; a++)
#pragma unroll
        for (int b = 0; b < 4; b++)
#pragma unroll
            for (int d = 0; d < 4; d++) { cc[a][b][d] = 0.0f; s2[a][b][d] = 0.0f; }

    load_stage(0, 0);
    load_stage(1, 1);
    load_stage(2, 2);

    for (int kt = 0; kt < nk; kt++) {
        const int rem = nk - 1 - kt;
        if (rem >= 2) { CP_WAIT2(); } else if (rem == 1) { CP_WAIT1(); } else { CP_WAIT0(); }
        __syncthreads();

        const char* st = sm + (size_t)(kt & 3) * STG;
        const char* Ah_s = st;
        const char* Al_s = st + PLANE;
        const char* Bh_s = st + 2 * PLANE;
        const char* Bl_s = st + 3 * PLANE;

#pragma unroll
        for (int ks = 0; ks < 2; ks++) {
            const int kb = ks * 32 + tq * 4;   // byte offset of this thread's k-pair
            uint32_t ah[4][4], al[4][4], bh[4][2], bl[4][2];
#pragma unroll
            for (int mi = 0; mi < 4; mi++) {
                const int r = wm * 64 + mi * 16 + gid;
                const char* p0 = Ah_s + r * PB + kb;
                const char* p1 = Al_s + r * PB + kb;
                ah[mi][0] = *(const uint32_t*)(p0);
                ah[mi][1] = *(const uint32_t*)(p0 + 8 * PB);
                ah[mi][2] = *(const uint32_t*)(p0 + 16);
                ah[mi][3] = *(const uint32_t*)(p0 + 8 * PB + 16);
                al[mi][0] = *(const uint32_t*)(p1);
                al[mi][1] = *(const uint32_t*)(p1 + 8 * PB);
                al[mi][2] = *(const uint32_t*)(p1 + 16);
                al[mi][3] = *(const uint32_t*)(p1 + 8 * PB + 16);
            }
#pragma unroll
            for (int ni = 0; ni < 4; ni++) {
                const int nrow = wn * 32 + ni * 8 + gid;
                const char* p0 = Bh_s + nrow * PB + kb;
                const char* p1 = Bl_s + nrow * PB + kb;
                bh[ni][0] = *(const uint32_t*)(p0);
                bh[ni][1] = *(const uint32_t*)(p0 + 16);
                bl[ni][0] = *(const uint32_t*)(p1);
                bl[ni][1] = *(const uint32_t*)(p1 + 16);
            }
#pragma unroll
            for (int mi = 0; mi < 4; mi++)
#pragma unroll
                for (int ni = 0; ni < 4; ni++) {
                    MMA_F16(cc[mi][ni][0], cc[mi][ni][1], cc[mi][ni][2], cc[mi][ni][3],
                            ah[mi][0], ah[mi][1], ah[mi][2], ah[mi][3],
                            bh[ni][0], bh[ni][1]);
                    MMA_F16(s2[mi][ni][0], s2[mi][ni][1], s2[mi][ni][2], s2[mi][ni][3],
                            ah[mi][0], ah[mi][1], ah[mi][2], ah[mi][3],
                            bl[ni][0], bl[ni][1]);
                    MMA_F16(s2[mi][ni][0], s2[mi][ni][1], s2[mi][ni][2], s2[mi][ni][3],
                            al[mi][0], al[mi][1], al[mi][2], al[mi][3],
                            bh[ni][0], bh[ni][1]);
                }
        }

        if (kt + 3 < nk) load_stage(kt + 3, (kt + 3) & 3);
    }

    // For EPI==1 we reuse pipeline smem as a 128x129 f32 staging tile; a fast
    // warp must not overwrite a slow warp's operands -> barrier first.
    if (EPI == 1) __syncthreads();
    float* smf = (float*)sm;

    // ---- epilogue ----
#pragma unroll
    for (int mi = 0; mi < 4; mi++) {
        const int row0 = m0 + wm * 64 + mi * 16 + gid;
        const int rl0  = wm * 64 + mi * 16 + gid;
#pragma unroll
        for (int ni = 0; ni < 4; ni++) {
            const int coll = wn * 32 + ni * 8 + tq * 2;
            const int col  = n0 + coll;
            const float bb0 = __ldg(bias + col);
            const float bb1 = __ldg(bias + col + 1);
            float v00 = fmaf(s2[mi][ni][0], RSCALE_I, cc[mi][ni][0]) + bb0;
            float v01 = fmaf(s2[mi][ni][1], RSCALE_I, cc[mi][ni][1]) + bb1;
            float v10 = fmaf(s2[mi][ni][2], RSCALE_I, cc[mi][ni][2]) + bb0;
            float v11 = fmaf(s2[mi][ni][3], RSCALE_I, cc[mi][ni][3]) + bb1;
            if (EPI == 0) {
                const float g00 = gelu_f(v00), g01 = gelu_f(v01);
                const float g10 = gelu_f(v10), g11 = gelu_f(v11);
                const __half h00 = __float2half_rn(g00), h01 = __float2half_rn(g01);
                const __half h10 = __float2half_rn(g10), h11 = __float2half_rn(g11);
                __half2 hl0; hl0.x = h00; hl0.y = h01;
                __half2 hl1; hl1.x = h10; hl1.y = h11;
                *(__half2*)(Ohi + (size_t)row0 * N + col)       = hl0;
                *(__half2*)(Ohi + (size_t)(row0 + 8) * N + col) = hl1;
                __half2 ll0, ll1;
                ll0.x = __float2half_rn((g00 - __half2float(h00)) * RSCALE);
                ll0.y = __float2half_rn((g01 - __half2float(h01)) * RSCALE);
                ll1.x = __float2half_rn((g10 - __half2float(h10)) * RSCALE);
                ll1.y = __float2half_rn((g11 - __half2float(h11)) * RSCALE);
                *(__half2*)(Olo + (size_t)row0 * N + col)       = ll0;
                *(__half2*)(Olo + (size_t)(row0 + 8) * N + col) = ll1;
            } else {
                const float c00 = sig2_f(v00), c01 = sig2_f(v01);
                const float c10 = sig2_f(v10), c11 = sig2_f(v11);
                *(float2*)(Oc + (size_t)row0 * N + col)       = make_float2(c00, c01);
                *(float2*)(Oc + (size_t)(row0 + 8) * N + col) = make_float2(c10, c11);
                smf[rl0 * 129 + coll]           = c00;
                smf[rl0 * 129 + coll + 1]       = c01;
                smf[(rl0 + 8) * 129 + coll]     = c10;
                smf[(rl0 + 8) * 129 + coll + 1] = c11;
            }
        }
    }

    if (EPI == 1) {
        __syncthreads();
        // one thread per (row, group): 128 rows x 2 groups = 256 threads
        const int r   = tid & 127;
        const int grp = tid >> 7;
        const float* p = smf + r * 129 + grp * 64;
        float v1 = -1e30f, v2 = -1e30f;
        int i1 = 0, i2 = 0;
#pragma unroll 8
        for (int i = 0; i < POOL; i++) {
            float v = p[i];
            if (v > v1) { v2 = v1; i2 = i1; v1 = v; i1 = i; }
            else if (v > v2) { v2 = v; i2 = i; }
        }
        const int row_g = m0 + r;
        const int grp_g = (n0 >> 6) + grp;
        const size_t o = (size_t)row_g * (NGRP * TOPK) + grp_g * TOPK;
        Tv[o]     = v1;
        Tv[o + 1] = v2;
        Ti[o]     = (float)i1;
        Ti[o + 1] = (float)i2;
    }
}

// ---------------- prepass: fp32 -> hi/lo fp16 planes (lo pre-scaled 2^11) ----------------
__global__ void split16_kernel(const float4* __restrict__ in,
                               __half* __restrict__ hi, __half* __restrict__ lo, int n4) {
    int i = blockIdx.x * blockDim.x + threadIdx.x;
    if (i < n4) {
        float4 v = in[i];
        __half h0 = __float2half_rn(v.x), h1 = __float2half_rn(v.y);
        __half h2 = __float2half_rn(v.z), h3 = __float2half_rn(v.w);
        __half2 ha; ha.x = h0; ha.y = h1;
        __half2 hb; hb.x = h2; hb.y = h3;
        *(__half2*)(hi + 4 * (size_t)i)     = ha;
        *(__half2*)(hi + 4 * (size_t)i + 2) = hb;
        __half2 la, lb;
        la.x = __float2half_rn((v.x - __half2float(h0)) * RSCALE);
        la.y = __float2half_rn((v.y - __half2float(h1)) * RSCALE);
        lb.x = __float2half_rn((v.z - __half2float(h2)) * RSCALE);
        lb.y = __float2half_rn((v.w - __half2float(h3)) * RSCALE);
        *(__half2*)(lo + 4 * (size_t)i)     = la;
        *(__half2*)(lo + 4 * (size_t)i + 2) = lb;
    }
}

// ---------------- prepass: W[K,N] fp32 -> Wt hi/lo [N][K] fp16 (half2 stores) ----------------
// 64(K) x 32(N) tiles; writes are 128B-coalesced per warp.
__global__ void tsplit16_kernel(const float* __restrict__ W,
                                __half* __restrict__ hi, __half* __restrict__ lo,
                                int K, int N) {
    __shared__ float t[64][33];
    const int nb = blockIdx.x * 32, kb = blockIdx.y * 64;
    const int tx = threadIdx.x, ty = threadIdx.y;   // (32, 8)
#pragma unroll
    for (int r = ty; r < 64; r += 8)
        t[r][tx] = W[(size_t)(kb + r) * N + nb + tx];
    __syncthreads();
#pragma unroll
    for (int n = ty; n < 32; n += 8) {
        const float v0 = t[2 * tx][n];       // = W[kb+2tx][nb+n]
        const float v1 = t[2 * tx + 1][n];
        const __half h0 = __float2half_rn(v0);
        const __half h1 = __float2half_rn(v1);
        __half2 hh; hh.x = h0; hh.y = h1;
        __half2 ll;
        ll.x = __float2half_rn((v0 - __half2float(h0)) * RSCALE);
        ll.y = __float2half_rn((v1 - __half2float(h1)) * RSCALE);
        const size_t base = (size_t)(nb + n) * K + kb + 2 * tx;
        *(__half2*)(hi + base) = hh;
        *(__half2*)(lo + base) = ll;
    }
}

// ---------------- launch ----------------
extern "C" void kernel_launch(void* const* d_in, const int* in_sizes, int n_in,
                              void* d_out, int out_size)
{
    const float* q  = (const float*)d_in[0];
    const float* W1 = (const float*)d_in[1];
    const float* b1 = (const float*)d_in[2];
    const float* W2 = (const float*)d_in[3];
    const float* b2 = (const float*)d_in[4];
    const float* W3 = (const float*)d_in[5];
    const float* b3 = (const float*)d_in[6];
    float* out = (float*)d_out;

    static bool configured = false;
    static __half *qh, *ql, *w1h, *w1l, *w2h, *w2l, *w3h, *w3l, *h1h, *h1l, *h2h, *h2l;
    if (!configured) {
        cudaGetSymbolAddress((void**)&qh,  g_qh);  cudaGetSymbolAddress((void**)&ql,  g_ql);
        cudaGetSymbolAddress((void**)&w1h, g_w1h); cudaGetSymbolAddress((void**)&w1l, g_w1l);
        cudaGetSymbolAddress((void**)&w2h, g_w2h); cudaGetSymbolAddress((void**)&w2l, g_w2l);
        cudaGetSymbolAddress((void**)&w3h, g_w3h); cudaGetSymbolAddress((void**)&w3l, g_w3l);
        cudaGetSymbolAddress((void**)&h1h, g_h1h); cudaGetSymbolAddress((void**)&h1l, g_h1l);
        cudaGetSymbolAddress((void**)&h2h, g_h2h); cudaGetSymbolAddress((void**)&h2l, g_h2l);
        cudaFuncSetAttribute(gemm_h<0>, cudaFuncAttributeMaxDynamicSharedMemorySize, GSMEM);
        cudaFuncSetAttribute(gemm_h<1>, cudaFuncAttributeMaxDynamicSharedMemorySize, GSMEM);
        configured = true;
    }

    float* tv = out + (size_t)BROWS * ODIM;
    float* ti = tv + (size_t)BROWS * NGRP * TOPK;

    // 1) prepasses: query split + weight transpose-splits
    {
        int n4 = (BROWS * INDIM) / 4;
        split16_kernel<<<(n4 + 255) / 256, 256>>>((const float4*)q, qh, ql, n4);
    }
    dim3 tb(32, 8);
    tsplit16_kernel<<<dim3(HID / 32, INDIM / 64), tb>>>(W1, w1h, w1l, INDIM, HID);
    tsplit16_kernel<<<dim3(HID / 32, HID / 64),  tb>>>(W2, w2h, w2l, HID,  HID);
    tsplit16_kernel<<<dim3(ODIM / 32, HID / 64), tb>>>(W3, w3h, w3l, HID,  ODIM);

    // 2) three GEMMs; GEMM3 also produces per-group top-2 in its epilogue
    dim3 blk(256);
    gemm_h<0><<<dim3(HID / 128, BROWS / 128), blk, GSMEM>>>(
        qh, ql, w1h, w1l, b1, h1h, h1l, nullptr, nullptr, nullptr, HID, INDIM, INDIM / 32);
    gemm_h<0><<<dim3(HID / 128, BROWS / 128), blk, GSMEM>>>(
        h1h, h1l, w2h, w2l, b2, h2h, h2l, nullptr, nullptr, nullptr, HID, HID, HID / 32);
    gemm_h<1><<<dim3(ODIM / 128, BROWS / 128), blk, GSMEM>>>(
        h2h, h2l, w3h, w3l, b3, nullptr, nullptr, out, tv, ti, ODIM, HID, HID / 32);
}

// round 14
// speedup vs baseline: 2.2397x; 1.0002x over previous
#include <cuda_runtime.h>
#include <cuda_fp16.h>
#include <cstdint>
#include <cstddef>

// Problem constants
#define BROWS 16384
#define INDIM 1024
#define HID   4096
#define ODIM  384
#define NGRP  6
#define POOL  64
#define TOPK  2

#define RSCALE   2048.0f          // 2^11: residual pre-scale
#define RSCALE_I 0.00048828125f   // 2^-11

// ---------------- scratch (device globals; no allocation allowed) ----------------
// hi/lo fp16 planes. Weights stored transposed [N][K] for .col B fragments.
__device__ __align__(16) __half g_qh[(size_t)BROWS * INDIM];
__device__ __align__(16) __half g_ql[(size_t)BROWS * INDIM];
__device__ __align__(16) __half g_w1h[(size_t)HID * INDIM];
__device__ __align__(16) __half g_w1l[(size_t)HID * INDIM];
__device__ __align__(16) __half g_w2h[(size_t)HID * HID];
__device__ __align__(16) __half g_w2l[(size_t)HID * HID];
__device__ __align__(16) __half g_w3h[(size_t)ODIM * HID];
__device__ __align__(16) __half g_w3l[(size_t)ODIM * HID];
__device__ __align__(16) __half g_h1h[(size_t)BROWS * HID];
__device__ __align__(16) __half g_h1l[(size_t)BROWS * HID];
__device__ __align__(16) __half g_h2h[(size_t)BROWS * HID];
__device__ __align__(16) __half g_h2l[(size_t)BROWS * HID];

// ---------------- helpers ----------------
__device__ __forceinline__ float gelu_f(float x) {
    float t = tanhf(0.7978845608028654f * (x + 0.044715f * x * x * x));
    return 0.5f * x * (1.0f + t);
}
__device__ __forceinline__ float sig2_f(float x) {
    return 2.0f / (1.0f + expf(-x));
}

#define CP_ASYNC16(dst, src) \
    asm volatile("cp.async.cg.shared.global [%0], [%1], 16;\n" :: "r"(dst), "l"(src) : "memory")
#define CP_COMMIT() asm volatile("cp.async.commit_group;\n" ::: "memory")
#define CP_WAIT2()  asm volatile("cp.async.wait_group 2;\n" ::: "memory")
#define CP_WAIT1()  asm volatile("cp.async.wait_group 1;\n" ::: "memory")
#define CP_WAIT0()  asm volatile("cp.async.wait_group 0;\n" ::: "memory")

#define MMA_F16(C0, C1, C2, C3, A0, A1, A2, A3, B0, B1) \
    asm volatile( \
        "mma.sync.aligned.m16n8k16.row.col.f32.f16.f16.f32 " \
        "{%0,%1,%2,%3}, {%4,%5,%6,%7}, {%8,%9}, {%0,%1,%2,%3};\n" \
        : "+f"(C0), "+f"(C1), "+f"(C2), "+f"(C3) \
        : "r"(A0), "r"(A1), "r"(A2), "r"(A3), "r"(B0), "r"(B1))

// ---------------- smem: 4 stages, BK=32, pitch 80B (40 half) ----------------
// stage: Ah[128][40] | Al | Bh[128][40] | Bl  (each 10240 B) = 40960 B
#define PB    80          // row pitch bytes
#define PLANE 10240
#define STG   40960
#define GSMEM (4 * STG)   // 163840 B  (also covers 128x129 f32 topk stage = 66048 B)

// ---------------- 3-product fp16-split GEMM ----------------
// A planes: [M][K] fp16 (hi, lo*2^11). B planes: Wt [N][K] fp16.
// cc += ah*bh ; s2 += ah*bl + al*bh ; result = cc + s2*2^-11 + bias
// MMAs issued as three full (mi,ni) sweeps so same-accumulator updates are
// 16 MMAs apart (hides HMMA latency). Per-accumulator addition order is
// unchanged vs the fused form -> bit-identical results.
// EPI==0: gelu -> write hi/lo fp16 planes.
// EPI==1: 2*sigmoid -> fp32 coeff + in-CTA per-group top-2 (tv/ti).
template <int EPI>
__global__ __launch_bounds__(256, 1) void gemm_h(
    const __half* __restrict__ Ah_g, const __half* __restrict__ Al_g,
    const __half* __restrict__ Bh_g, const __half* __restrict__ Bl_g,
    const float* __restrict__ bias,
    __half* __restrict__ Ohi, __half* __restrict__ Olo, float* __restrict__ Oc,
    float* __restrict__ Tv, float* __restrict__ Ti,
    int N, int K, int nk)
{
    extern __shared__ char sm[];
    const uint32_t sbase = (uint32_t)__cvta_generic_to_shared(sm);

    const int tid  = threadIdx.x;
    const int lane = tid & 31;
    const int warp = tid >> 5;
    const int wm = warp & 1;      // 2 warp rows (64 each)
    const int wn = warp >> 1;     // 4 warp cols (32 each)
    const int gid = lane >> 2;    // 0..7
    const int tq  = lane & 3;     // 0..3

    const int m0 = blockIdx.y * 128;
    const int n0 = blockIdx.x * 128;

    auto load_stage = [&](int kt, int s) {
        const uint32_t st = sbase + (uint32_t)s * STG;
#pragma unroll
        for (int p = 0; p < 2; p++) {
            const int c = p * 256 + tid;        // 0..511
            const int row = c >> 2, kc = c & 3; // 128 rows x 4 chunks of 16B (8 half)
            const uint32_t off = (uint32_t)(row * PB + kc * 16);
            const size_t ga = (size_t)(m0 + row) * K + kt * 32 + kc * 8;
            const size_t gb = (size_t)(n0 + row) * K + kt * 32 + kc * 8;
            CP_ASYNC16(st + 0 * PLANE + off, Ah_g + ga);
            CP_ASYNC16(st + 1 * PLANE + off, Al_g + ga);
            CP_ASYNC16(st + 2 * PLANE + off, Bh_g + gb);
            CP_ASYNC16(st + 3 * PLANE + off, Bl_g + gb);
        }
        CP_COMMIT();
    };

    float cc[4][4][4];   // ah*bh
    float s2[4][4][4];   // ah*bl + al*bh  (pre-scaled by 2^11)
#pragma unroll
    for (int a = 0; a < 4; a++)
#pragma unroll
        for (int b = 0; b < 4; b++)
#pragma unroll
            for (int d = 0; d < 4; d++) { cc[a][b][d] = 0.0f; s2[a][b][d] = 0.0f; }

    load_stage(0, 0);
    load_stage(1, 1);
    load_stage(2, 2);

    for (int kt = 0; kt < nk; kt++) {
        const int rem = nk - 1 - kt;
        if (rem >= 2) { CP_WAIT2(); } else if (rem == 1) { CP_WAIT1(); } else { CP_WAIT0(); }
        __syncthreads();

        const char* st = sm + (size_t)(kt & 3) * STG;
        const char* Ah_s = st;
        const char* Al_s = st + PLANE;
        const char* Bh_s = st + 2 * PLANE;
        const char* Bl_s = st + 3 * PLANE;

#pragma unroll
        for (int ks = 0; ks < 2; ks++) {
            const int kb = ks * 32 + tq * 4;   // byte offset of this thread's k-pair
            uint32_t ah[4][4], al[4][4], bh[4][2], bl[4][2];
#pragma unroll
            for (int mi = 0; mi < 4; mi++) {
                const int r = wm * 64 + mi * 16 + gid;
                const char* p0 = Ah_s + r * PB + kb;
                const char* p1 = Al_s + r * PB + kb;
                ah[mi][0] = *(const uint32_t*)(p0);
                ah[mi][1] = *(const uint32_t*)(p0 + 8 * PB);
                ah[mi][2] = *(const uint32_t*)(p0 + 16);
                ah[mi][3] = *(const uint32_t*)(p0 + 8 * PB + 16);
                al[mi][0] = *(const uint32_t*)(p1);
                al[mi][1] = *(const uint32_t*)(p1 + 8 * PB);
                al[mi][2] = *(const uint32_t*)(p1 + 16);
                al[mi][3] = *(const uint32_t*)(p1 + 8 * PB + 16);
            }
#pragma unroll
            for (int ni = 0; ni < 4; ni++) {
                const int nrow = wn * 32 + ni * 8 + gid;
                const char* p0 = Bh_s + nrow * PB + kb;
                const char* p1 = Bl_s + nrow * PB + kb;
                bh[ni][0] = *(const uint32_t*)(p0);
                bh[ni][1] = *(const uint32_t*)(p0 + 16);
                bl[ni][0] = *(const uint32_t*)(p1);
                bl[ni][1] = *(const uint32_t*)(p1 + 16);
            }
            // sweep 1: cc += ah*bh   (16 independent MMAs)
#pragma unroll
            for (int mi = 0; mi < 4; mi++)
#pragma unroll
                for (int ni = 0; ni < 4; ni++)
                    MMA_F16(cc[mi][ni][0], cc[mi][ni][1], cc[mi][ni][2], cc[mi][ni][3],
                            ah[mi][0], ah[mi][1], ah[mi][2], ah[mi][3],
                            bh[ni][0], bh[ni][1]);
            // sweep 2: s2 += ah*bl   (16 independent MMAs)
#pragma unroll
            for (int mi = 0; mi < 4; mi++)
#pragma unroll
                for (int ni = 0; ni < 4; ni++)
                    MMA_F16(s2[mi][ni][0], s2[mi][ni][1], s2[mi][ni][2], s2[mi][ni][3],
                            ah[mi][0], ah[mi][1], ah[mi][2], ah[mi][3],
                            bl[ni][0], bl[ni][1]);
            // sweep 3: s2 += al*bh   (dependent update now 16 MMAs away)
#pragma unroll
            for (int mi = 0; mi < 4; mi++)
#pragma unroll
                for (int ni = 0; ni < 4; ni++)
                    MMA_F16(s2[mi][ni][0], s2[mi][ni][1], s2[mi][ni][2], s2[mi][ni][3],
                            al[mi][0], al[mi][1], al[mi][2], al[mi][3],
                            bh[ni][0], bh[ni][1]);
        }

        if (kt + 3 < nk) load_stage(kt + 3, (kt + 3) & 3);
    }

    // For EPI==1 we reuse pipeline smem as a 128x129 f32 staging tile; a fast
    // warp must not overwrite a slow warp's operands -> barrier first.
    if (EPI == 1) __syncthreads();
    float* smf = (float*)sm;

    // ---- epilogue ----
#pragma unroll
    for (int mi = 0; mi < 4; mi++) {
        const int row0 = m0 + wm * 64 + mi * 16 + gid;
        const int rl0  = wm * 64 + mi * 16 + gid;
#pragma unroll
        for (int ni = 0; ni < 4; ni++) {
            const int coll = wn * 32 + ni * 8 + tq * 2;
            const int col  = n0 + coll;
            const float bb0 = __ldg(bias + col);
            const float bb1 = __ldg(bias + col + 1);
            float v00 = fmaf(s2[mi][ni][0], RSCALE_I, cc[mi][ni][0]) + bb0;
            float v01 = fmaf(s2[mi][ni][1], RSCALE_I, cc[mi][ni][1]) + bb1;
            float v10 = fmaf(s2[mi][ni][2], RSCALE_I, cc[mi][ni][2]) + bb0;
            float v11 = fmaf(s2[mi][ni][3], RSCALE_I, cc[mi][ni][3]) + bb1;
            if (EPI == 0) {
                const float g00 = gelu_f(v00), g01 = gelu_f(v01);
                const float g10 = gelu_f(v10), g11 = gelu_f(v11);
                const __half h00 = __float2half_rn(g00), h01 = __float2half_rn(g01);
                const __half h10 = __float2half_rn(g10), h11 = __float2half_rn(g11);
                __half2 hl0; hl0.x = h00; hl0.y = h01;
                __half2 hl1; hl1.x = h10; hl1.y = h11;
                *(__half2*)(Ohi + (size_t)row0 * N + col)       = hl0;
                *(__half2*)(Ohi + (size_t)(row0 + 8) * N + col) = hl1;
                __half2 ll0, ll1;
                ll0.x = __float2half_rn((g00 - __half2float(h00)) * RSCALE);
                ll0.y = __float2half_rn((g01 - __half2float(h01)) * RSCALE);
                ll1.x = __float2half_rn((g10 - __half2float(h10)) * RSCALE);
                ll1.y = __float2half_rn((g11 - __half2float(h11)) * RSCALE);
                *(__half2*)(Olo + (size_t)row0 * N + col)       = ll0;
                *(__half2*)(Olo + (size_t)(row0 + 8) * N + col) = ll1;
            } else {
                const float c00 = sig2_f(v00), c01 = sig2_f(v01);
                const float c10 = sig2_f(v10), c11 = sig2_f(v11);
                *(float2*)(Oc + (size_t)row0 * N + col)       = make_float2(c00, c01);
                *(float2*)(Oc + (size_t)(row0 + 8) * N + col) = make_float2(c10, c11);
                smf[rl0 * 129 + coll]           = c00;
                smf[rl0 * 129 + coll + 1]       = c01;
                smf[(rl0 + 8) * 129 + coll]     = c10;
                smf[(rl0 + 8) * 129 + coll + 1] = c11;
            }
        }
    }

    if (EPI == 1) {
        __syncthreads();
        // one thread per (row, group): 128 rows x 2 groups = 256 threads
        const int r   = tid & 127;
        const int grp = tid >> 7;
        const float* p = smf + r * 129 + grp * 64;
        float v1 = -1e30f, v2 = -1e30f;
        int i1 = 0, i2 = 0;
#pragma unroll 8
        for (int i = 0; i < POOL; i++) {
            float v = p[i];
            if (v > v1) { v2 = v1; i2 = i1; v1 = v; i1 = i; }
            else if (v > v2) { v2 = v; i2 = i; }
        }
        const int row_g = m0 + r;
        const int grp_g = (n0 >> 6) + grp;
        const size_t o = (size_t)row_g * (NGRP * TOPK) + grp_g * TOPK;
        Tv[o]     = v1;
        Tv[o + 1] = v2;
        Ti[o]     = (float)i1;
        Ti[o + 1] = (float)i2;
    }
}

// ---------------- prepass: fp32 -> hi/lo fp16 planes (lo pre-scaled 2^11) ----------------
__global__ void split16_kernel(const float4* __restrict__ in,
                               __half* __restrict__ hi, __half* __restrict__ lo, int n4) {
    int i = blockIdx.x * blockDim.x + threadIdx.x;
    if (i < n4) {
        float4 v = in[i];
        __half h0 = __float2half_rn(v.x), h1 = __float2half_rn(v.y);
        __half h2 = __float2half_rn(v.z), h3 = __float2half_rn(v.w);
        __half2 ha; ha.x = h0; ha.y = h1;
        __half2 hb; hb.x = h2; hb.y = h3;
        *(__half2*)(hi + 4 * (size_t)i)     = ha;
        *(__half2*)(hi + 4 * (size_t)i + 2) = hb;
        __half2 la, lb;
        la.x = __float2half_rn((v.x - __half2float(h0)) * RSCALE);
        la.y = __float2half_rn((v.y - __half2float(h1)) * RSCALE);
        lb.x = __float2half_rn((v.z - __half2float(h2)) * RSCALE);
        lb.y = __float2half_rn((v.w - __half2float(h3)) * RSCALE);
        *(__half2*)(lo + 4 * (size_t)i)     = la;
        *(__half2*)(lo + 4 * (size_t)i + 2) = lb;
    }
}

// ---------------- prepass: W[K,N] fp32 -> Wt hi/lo [N][K] fp16 (half2 stores) ----------------
// 64(K) x 32(N) tiles; writes are 128B-coalesced per warp.
__global__ void tsplit16_kernel(const float* __restrict__ W,
                                __half* __restrict__ hi, __half* __restrict__ lo,
                                int K, int N) {
    __shared__ float t[64][33];
    const int nb = blockIdx.x * 32, kb = blockIdx.y * 64;
    const int tx = threadIdx.x, ty = threadIdx.y;   // (32, 8)
#pragma unroll
    for (int r = ty; r < 64; r += 8)
        t[r][tx] = W[(size_t)(kb + r) * N + nb + tx];
    __syncthreads();
#pragma unroll
    for (int n = ty; n < 32; n += 8) {
        const float v0 = t[2 * tx][n];       // = W[kb+2tx][nb+n]
        const float v1 = t[2 * tx + 1][n];
        const __half h0 = __float2half_rn(v0);
        const __half h1 = __float2half_rn(v1);
        __half2 hh; hh.x = h0; hh.y = h1;
        __half2 ll;
        ll.x = __float2half_rn((v0 - __half2float(h0)) * RSCALE);
        ll.y = __float2half_rn((v1 - __half2float(h1)) * RSCALE);
        const size_t base = (size_t)(nb + n) * K + kb + 2 * tx;
        *(__half2*)(hi + base) = hh;
        *(__half2*)(lo + base) = ll;
    }
}

// ---------------- launch ----------------
extern "C" void kernel_launch(void* const* d_in, const int* in_sizes, int n_in,
                              void* d_out, int out_size)
{
    const float* q  = (const float*)d_in[0];
    const float* W1 = (const float*)d_in[1];
    const float* b1 = (const float*)d_in[2];
    const float* W2 = (const float*)d_in[3];
    const float* b2 = (const float*)d_in[4];
    const float* W3 = (const float*)d_in[5];
    const float* b3 = (const float*)d_in[6];
    float* out = (float*)d_out;

    static bool configured = false;
    static __half *qh, *ql, *w1h, *w1l, *w2h, *w2l, *w3h, *w3l, *h1h, *h1l, *h2h, *h2l;
    if (!configured) {
        cudaGetSymbolAddress((void**)&qh,  g_qh);  cudaGetSymbolAddress((void**)&ql,  g_ql);
        cudaGetSymbolAddress((void**)&w1h, g_w1h); cudaGetSymbolAddress((void**)&w1l, g_w1l);
        cudaGetSymbolAddress((void**)&w2h, g_w2h); cudaGetSymbolAddress((void**)&w2l, g_w2l);
        cudaGetSymbolAddress((void**)&w3h, g_w3h); cudaGetSymbolAddress((void**)&w3l, g_w3l);
        cudaGetSymbolAddress((void**)&h1h, g_h1h); cudaGetSymbolAddress((void**)&h1l, g_h1l);
        cudaGetSymbolAddress((void**)&h2h, g_h2h); cudaGetSymbolAddress((void**)&h2l, g_h2l);
        cudaFuncSetAttribute(gemm_h<0>, cudaFuncAttributeMaxDynamicSharedMemorySize, GSMEM);
        cudaFuncSetAttribute(gemm_h<1>, cudaFuncAttributeMaxDynamicSharedMemorySize, GSMEM);
        configured = true;
    }

    float* tv = out + (size_t)BROWS * ODIM;
    float* ti = tv + (size_t)BROWS * NGRP * TOPK;

    // 1) prepasses: query split + weight transpose-splits
    {
        int n4 = (BROWS * INDIM) / 4;
        split16_kernel<<<(n4 + 255) / 256, 256>>>((const float4*)q, qh, ql, n4);
    }
    dim3 tb(32, 8);
    tsplit16_kernel<<<dim3(HID / 32, INDIM / 64), tb>>>(W1, w1h, w1l, INDIM, HID);
    tsplit16_kernel<<<dim3(HID / 32, HID / 64),  tb>>>(W2, w2h, w2l, HID,  HID);
    tsplit16_kernel<<<dim3(ODIM / 32, HID / 64), tb>>>(W3, w3h, w3l, HID,  ODIM);

    // 2) three GEMMs; GEMM3 also produces per-group top-2 in its epilogue
    dim3 blk(256);
    gemm_h<0><<<dim3(HID / 128, BROWS / 128), blk, GSMEM>>>(
        qh, ql, w1h, w1l, b1, h1h, h1l, nullptr, nullptr, nullptr, HID, INDIM, INDIM / 32);
    gemm_h<0><<<dim3(HID / 128, BROWS / 128), blk, GSMEM>>>(
        h1h, h1l, w2h, w2l, b2, h2h, h2l, nullptr, nullptr, nullptr, HID, HID, HID / 32);
    gemm_h<1><<<dim3(ODIM / 128, BROWS / 128), blk, GSMEM>>>(
        h2h, h2l, w3h, w3l, b3, nullptr, nullptr, out, tv, ti, ODIM, HID, HID / 32);
}